// round 5
// baseline (speedup 1.0000x reference)
#include <cuda_runtime.h>

#define SQ   1024   // spatial sequence length (16*64)
#define CH   64     // channels == heads (c = 1 per head)
#define BB   2      // batch
#define NHB  128    // b*g head-batches
#define M    16     // Chebyshev nodes / polynomial terms
#define NBLK 128
#define NTHR 512
#define CSTR 36     // per-head coefficient stride: ca[16] cb[16] cc invr

// Scratch (allocation-free rule: __device__ globals)
__device__ float g_q[NHB * SQ];
__device__ float g_k[NHB * SQ];      // pre-scaled by log2(e)/8
__device__ float g_v[NHB * SQ];
__device__ float g_coef[NHB * CSTR];

__device__ unsigned          g_bar_count[2] = {0u, 0u};
__device__ volatile unsigned g_bar_epoch[2] = {0u, 0u};

__device__ __forceinline__ float ex2f(float x) {
    float r;
    asm("ex2.approx.ftz.f32 %0, %1;" : "=f"(r) : "f"(x));
    return r;
}

// Sense-reversing grid barrier. Safe: 128 blocks <= 148 SMs, all co-resident.
// Every thread fences its own writes to gpu scope before arriving; the
// epoch counter increases monotonically across graph replays (count resets).
__device__ __forceinline__ void grid_barrier(int which) {
    __threadfence();
    __syncthreads();
    if (threadIdx.x == 0) {
        unsigned e = g_bar_epoch[which];
        unsigned t = atomicAdd(&g_bar_count[which], 1u);
        if (t == NBLK - 1) {
            g_bar_count[which] = 0u;
            __threadfence();
            g_bar_epoch[which] = e + 1u;
        } else {
            while (g_bar_epoch[which] == e) { }
        }
    }
    __syncthreads();
    __threadfence();
}

__global__ __launch_bounds__(NTHR) void fused_all(
    const float* __restrict__ x,
    const float* __restrict__ Wq, const float* __restrict__ bq,
    const float* __restrict__ Wk, const float* __restrict__ bk,
    const float* __restrict__ Wv, const float* __restrict__ bv,
    const float* __restrict__ Wo, const float* __restrict__ bo,
    float* __restrict__ outp)
{
    __shared__ union {
        struct {                        // Phase A / C GEMM layout
            float WT[CH][CH + 1];       // transposed weights, padded
            float xt[CH][16];           // input / o tile
            float ca[CH][M];            // (C only) per-head coefficients
            float cb[CH][M];
            float cc[CH];
            float ir[CH];
        } g;
        struct {                        // Phase B layout
            float kh[SQ];
            float vv[SQ];
            float fj[M], gj[M];
            float rmin[16], rmax[16];
            float sc[4];
        } a;
    } sm;

    const int tid = threadIdx.x;
    const float KS = 0.18033688011112042f;   // log2(e) / sqrt(64)

    // =====================================================================
    // Phase A: QKV projections. Block = (b, 16-s tile). x tile read once.
    // =====================================================================
    {
        const int b  = blockIdx.x >> 6;
        const int s0 = (blockIdx.x & 63) * 16;

        // stage x tile: thread (c = tid>>3, j2 = tid&7) loads one float2
        {
            const int c = tid >> 3, j2 = tid & 7;
            float2 xv = *reinterpret_cast<const float2*>(
                x + (size_t)(b * CH + c) * SQ + s0 + 2 * j2);
            sm.g.xt[c][2 * j2]     = xv.x;
            sm.g.xt[c][2 * j2 + 1] = xv.y;
        }

        const float* Wm[3] = {Wq, Wk, Wv};
        const float* Bm[3] = {bq, bk, bv};
        float*       Dm[3] = {g_q, g_k, g_v};

        const int o  = tid >> 3;       // output channel / head
        const int sp = tid & 7;        // s-pair within tile

#pragma unroll
        for (int m = 0; m < 3; m++) {
            __syncthreads();
            // stage W transposed: WT[c][o] = W[o][c], conflict-free stores
#pragma unroll
            for (int i = tid; i < CH * CH; i += NTHR)
                sm.g.WT[i & 63][i >> 6] = Wm[m][i];
            __syncthreads();

            float bias = Bm[m][o];
            float ax = bias, ay = bias;
#pragma unroll
            for (int c = 0; c < CH; c++) {
                float w  = sm.g.WT[c][o];
                ax = fmaf(w, sm.g.xt[c][2 * sp],     ax);
                ay = fmaf(w, sm.g.xt[c][2 * sp + 1], ay);
            }
            if (m == 1) { ax *= KS; ay *= KS; }
            float2 r; r.x = ax; r.y = ay;
            *reinterpret_cast<float2*>(
                Dm[m] + (size_t)(b * CH + o) * SQ + s0 + 2 * sp) = r;
        }
    }

    grid_barrier(0);

    // =====================================================================
    // Phase B: per-head Chebyshev coefficients. Block = head hb.
    // =====================================================================
    {
        const int hb = blockIdx.x;
        const int w  = tid >> 5, l = tid & 31;

        // stage k (pre-scaled), v; reduce q min/max
        float2 kk = reinterpret_cast<const float2*>(g_k + (size_t)hb * SQ)[tid];
        float2 vv = reinterpret_cast<const float2*>(g_v + (size_t)hb * SQ)[tid];
        reinterpret_cast<float2*>(sm.a.kh)[tid] = kk;
        reinterpret_cast<float2*>(sm.a.vv)[tid] = vv;
        float2 qq = reinterpret_cast<const float2*>(g_q + (size_t)hb * SQ)[tid];
        float qmn = fminf(qq.x, qq.y);
        float qmx = fmaxf(qq.x, qq.y);
#pragma unroll
        for (int d = 16; d; d >>= 1) {
            qmn = fminf(qmn, __shfl_xor_sync(0xffffffffu, qmn, d));
            qmx = fmaxf(qmx, __shfl_xor_sync(0xffffffffu, qmx, d));
        }
        if (l == 0) { sm.a.rmin[w] = qmn; sm.a.rmax[w] = qmx; }
        __syncthreads();
        if (tid == 0) {
            float mn = sm.a.rmin[0], mx = sm.a.rmax[0];
#pragma unroll
            for (int i = 1; i < 16; i++) {
                mn = fminf(mn, sm.a.rmin[i]);
                mx = fmaxf(mx, sm.a.rmax[i]);
            }
            float c0 = 0.5f * (mn + mx);
            float r0 = fmaxf(0.5f * (mx - mn), 1e-4f);
            sm.a.sc[0] = c0; sm.a.sc[1] = r0; sm.a.sc[2] = 1.0f / r0;
        }
        __syncthreads();
        const float cc = sm.a.sc[0], rr = sm.a.sc[1], invr = sm.a.sc[2];

        // node evaluation: warp w -> node w
        {
            const float PI_M = 3.14159265358979f / (float)M;
            const float xj = cc + rr * cosf(((float)w + 0.5f) * PI_M);
            float f0 = 0.f, g0 = 0.f;
#pragma unroll 8
            for (int t = l; t < SQ; t += 32) {
                float e0 = ex2f(xj * sm.a.kh[t]);
                f0 += e0;
                g0 = fmaf(e0, sm.a.vv[t], g0);
            }
#pragma unroll
            for (int d = 16; d; d >>= 1) {
                f0 += __shfl_xor_sync(0xffffffffu, f0, d);
                g0 += __shfl_xor_sync(0xffffffffu, g0, d);
            }
            if (l == 0) { sm.a.fj[w] = f0; sm.a.gj[w] = g0; }
        }
        __syncthreads();

        // DCT -> coefficients, write to g_coef
        if (tid < M) {
            const float PI_M = 3.14159265358979f / (float)M;
            float af = 0.f, ag = 0.f;
#pragma unroll
            for (int j = 0; j < M; j++) {
                float wgt = cosf((float)tid * ((float)j + 0.5f) * PI_M);
                af = fmaf(sm.a.fj[j], wgt, af);
                ag = fmaf(sm.a.gj[j], wgt, ag);
            }
            float scale = (tid == 0) ? (1.0f / M) : (2.0f / M);
            g_coef[hb * CSTR + tid]      = af * scale;
            g_coef[hb * CSTR + M + tid]  = ag * scale;
            if (tid == 0) {
                g_coef[hb * CSTR + 32] = cc;
                g_coef[hb * CSTR + 33] = invr;
            }
        }
    }

    grid_barrier(1);

    // =====================================================================
    // Phase C: Clenshaw -> o tile -> Wo GEMM + residual. Block = (b, tile).
    // =====================================================================
    {
        const int b  = blockIdx.x >> 6;
        const int s0 = (blockIdx.x & 63) * 16;

        // stage Wo transposed
#pragma unroll
        for (int i = tid; i < CH * CH; i += NTHR)
            sm.g.WT[i & 63][i >> 6] = Wo[i];

        // stage per-head coefficients for this batch
        for (int i = tid; i < CH * CSTR; i += NTHR) {
            int h = i / CSTR, r = i - h * CSTR;
            float v = g_coef[(b * CH + h) * CSTR + r];
            if (r < M)            sm.g.ca[h][r]      = v;
            else if (r < 2 * M)   sm.g.cb[h][r - M]  = v;
            else if (r == 32)     sm.g.cc[h]         = v;
            else if (r == 33)     sm.g.ir[h]         = v;
        }
        __syncthreads();

        // Clenshaw: items (h, si), 2 per thread; ot[h][si] conflict-free
#pragma unroll
        for (int i = tid; i < CH * 16; i += NTHR) {
            int h = i >> 4, si = i & 15;
            float q = g_q[(size_t)(b * CH + h) * SQ + s0 + si];
            float u  = (q - sm.g.cc[h]) * sm.g.ir[h];
            float u2 = 2.f * u;
            float b1 = 0.f, b2 = 0.f, d1 = 0.f, d2 = 0.f;
#pragma unroll
            for (int k = M - 1; k >= 1; k--) {
                float tb = fmaf(u2, b1, sm.g.ca[h][k] - b2); b2 = b1; b1 = tb;
                float td = fmaf(u2, d1, sm.g.cb[h][k] - d2); d2 = d1; d1 = td;
            }
            float f = fmaf(u, b1, sm.g.ca[h][0] - b2);
            float g = fmaf(u, d1, sm.g.cb[h][0] - d2);
            sm.g.xt[h][si] = __fdividef(g, f);
        }
        __syncthreads();

        // output projection + residual
        const int o  = tid >> 3;
        const int sp = tid & 7;
        float bias = bo[o];
        float ax = bias, ay = bias;
#pragma unroll
        for (int c = 0; c < CH; c++) {
            float w = sm.g.WT[c][o];
            ax = fmaf(w, sm.g.xt[c][2 * sp],     ax);
            ay = fmaf(w, sm.g.xt[c][2 * sp + 1], ay);
        }
        const size_t idx = (size_t)(b * CH + o) * SQ + s0 + 2 * sp;
        float2 rv = *reinterpret_cast<const float2*>(x + idx);
        ax += rv.x; ay += rv.y;
        float2 o2; o2.x = ax; o2.y = ay;
        *reinterpret_cast<float2*>(outp + idx) = o2;
    }
}

extern "C" void kernel_launch(void* const* d_in, const int* in_sizes, int n_in,
                              void* d_out, int out_size)
{
    const float* x  = (const float*)d_in[0];
    const float* Wq = (const float*)d_in[1];
    const float* bq = (const float*)d_in[2];
    const float* Wk = (const float*)d_in[3];
    const float* bk = (const float*)d_in[4];
    const float* Wv = (const float*)d_in[5];
    const float* bv = (const float*)d_in[6];
    const float* Wo = (const float*)d_in[7];
    const float* bo = (const float*)d_in[8];
    float* out = (float*)d_out;

    fused_all<<<NBLK, NTHR>>>(x, Wq, bq, Wk, bk, Wv, bv, Wo, bo, out);
}